// round 5
// baseline (speedup 1.0000x reference)
#include <cuda_runtime.h>
#include <cuda_bf16.h>

// Problem constants (from reference setup_inputs)
#define BB 4
#define TT 4096
#define DD 2048
#define D4 512          // DD / 4 float4 lanes
#define CT 32           // time-rows per block (plus 3 halo rows)
#define EPS 1e-5f

__global__ __launch_bounds__(512)
void fused_rms_dwconv_silu(const float* __restrict__ x,
                           const float* __restrict__ nw,
                           const float* __restrict__ cw,
                           float* __restrict__ out) {
    // Double-buffered warp-partial staging: 16 partials per phase.
    __shared__ float sm[32];

    const int d4   = threadIdx.x;        // 0..511 (float4 lane over D)
    const int lane = threadIdx.x & 31;
    const int wrp  = threadIdx.x >> 5;   // 0..15
    const int b    = blockIdx.y;         // batch
    const int t0   = blockIdx.x * CT;    // first output row of this chunk
    const int d    = d4 * 4;

    // Conv taps per channel with norm_weight folded in:
    // out = sum_k w[d,k] * (x * rinv * nw[d]) == sum_k (w[d,k]*nw[d]) * (x * rinv)
    float4 w0 = *(const float4*)(cw + (size_t)(d + 0) * 4);
    float4 w1 = *(const float4*)(cw + (size_t)(d + 1) * 4);
    float4 w2 = *(const float4*)(cw + (size_t)(d + 2) * 4);
    float4 w3 = *(const float4*)(cw + (size_t)(d + 3) * 4);
    const float n0 = nw[d], n1 = nw[d + 1], n2 = nw[d + 2], n3 = nw[d + 3];
    w0.x *= n0; w0.y *= n0; w0.z *= n0; w0.w *= n0;
    w1.x *= n1; w1.y *= n1; w1.z *= n1; w1.w *= n1;
    w2.x *= n2; w2.y *= n2; w2.z *= n2; w2.w *= n2;
    w3.x *= n3; w3.y *= n3; w3.z *= n3; w3.w *= n3;

    const float4* xp = (const float4*)x + (size_t)b * TT * D4 + d4;
    float4*       op = (float4*)out     + (size_t)b * TT * D4 + d4;

    // Sliding window of normalized rows: y0=y[t-3], y1=y[t-2], y2=y[t-1]
    float4 y0 = make_float4(0.f, 0.f, 0.f, 0.f);
    float4 y1 = y0, y2 = y0;

    int t = t0 - 3;
    float4 xv = (t >= 0) ? __ldg(xp + (size_t)t * D4)
                         : make_float4(0.f, 0.f, 0.f, 0.f);

    #pragma unroll 1
    for (int i = 0; i < CT + 3; i++, t++) {
        // Prefetch next row before the reduction (independent of it).
        float4 xn = make_float4(0.f, 0.f, 0.f, 0.f);
        if (i + 1 < CT + 3 && t + 1 >= 0)
            xn = __ldg(xp + (size_t)(t + 1) * D4);

        // ---- block reduction over D (one barrier, double-buffered) ----
        float v = xv.x * xv.x + xv.y * xv.y + xv.z * xv.z + xv.w * xv.w;
        #pragma unroll
        for (int o = 16; o; o >>= 1) v += __shfl_xor_sync(0xffffffffu, v, o);

        float* buf = sm + ((i & 1) << 4);
        if (lane == 0) buf[wrp] = v;
        __syncthreads();

        float tot = 0.f;
        #pragma unroll
        for (int j = 0; j < 16; j++) tot += buf[j];   // broadcast LDS

        const float r = rsqrtf(tot * (1.0f / (float)DD) + EPS);
        float4 y3 = make_float4(xv.x * r, xv.y * r, xv.z * r, xv.w * r);

        if (i >= 3) {   // output rows t0 .. t0+CT-1
            float4 o;
            o.x = w0.x * y0.x + w0.y * y1.x + w0.z * y2.x + w0.w * y3.x;
            o.y = w1.x * y0.y + w1.y * y1.y + w1.z * y2.y + w1.w * y3.y;
            o.z = w2.x * y0.z + w2.y * y1.z + w2.z * y2.z + w2.w * y3.z;
            o.w = w3.x * y0.w + w3.y * y1.w + w3.z * y2.w + w3.w * y3.w;
            // SiLU
            o.x = o.x / (1.0f + __expf(-o.x));
            o.y = o.y / (1.0f + __expf(-o.y));
            o.z = o.z / (1.0f + __expf(-o.z));
            o.w = o.w / (1.0f + __expf(-o.w));
            op[(size_t)t * D4] = o;
        }

        y0 = y1; y1 = y2; y2 = y3; xv = xn;
    }
}

extern "C" void kernel_launch(void* const* d_in, const int* in_sizes, int n_in,
                              void* d_out, int out_size) {
    const float* x  = (const float*)d_in[0];   // [B, T, D] fp32
    const float* nw = (const float*)d_in[1];   // [D] fp32
    const float* cw = (const float*)d_in[2];   // [D, 1, K=4] fp32
    float* out = (float*)d_out;                // [B, T, D] fp32

    dim3 grid(TT / CT, BB);
    fused_rms_dwconv_silu<<<grid, 512>>>(x, nw, cw, out);
}

// round 6
// speedup vs baseline: 1.1152x; 1.1152x over previous
#include <cuda_runtime.h>
#include <cuda_bf16.h>

// Problem constants (from reference setup_inputs)
#define BB 4
#define TT 4096
#define DD 2048
#define D4 512          // DD / 4 float4 lanes
#define CT 64           // output rows per block
#define NPH 16          // main phases, 4 rows each
#define EPS 1e-5f

// sigmoid via MUFU.TANH (sm_75+): 1 MUFU instead of EX2+RCP.
__device__ __forceinline__ float fast_sigmoid(float v) {
    float t;
    asm("tanh.approx.f32 %0, %1;" : "=f"(t) : "f"(v * 0.5f));
    return fmaf(t, 0.5f, 0.5f);
}

__device__ __forceinline__ float warp_sum(float v) {
    #pragma unroll
    for (int o = 16; o; o >>= 1) v += __shfl_xor_sync(0xffffffffu, v, o);
    return v;
}

__device__ __forceinline__ float sq4(float4 a) {
    return a.x * a.x + a.y * a.y + a.z * a.z + a.w * a.w;
}

__global__ __launch_bounds__(512, 2)
void fused_rms_dwconv_silu(const float* __restrict__ x,
                           const float* __restrict__ nw,
                           const float* __restrict__ cw,
                           float* __restrict__ out) {
    __shared__ float  part[4 * 16];   // [row][warp] partials
    __shared__ float4 fin[2];         // double-buffered rinv packs

    const int tid  = threadIdx.x;     // 0..511, one float4 column of D
    const int lane = tid & 31;
    const int wrp  = tid >> 5;        // 0..15
    const int b    = blockIdx.y;
    const int t0   = blockIdx.x * CT;
    const int d    = tid * 4;

    // Conv taps with norm_weight folded in.
    float4 w0 = *(const float4*)(cw + (size_t)(d + 0) * 4);
    float4 w1 = *(const float4*)(cw + (size_t)(d + 1) * 4);
    float4 w2 = *(const float4*)(cw + (size_t)(d + 2) * 4);
    float4 w3 = *(const float4*)(cw + (size_t)(d + 3) * 4);
    const float n0 = nw[d], n1 = nw[d + 1], n2 = nw[d + 2], n3 = nw[d + 3];
    w0.x *= n0; w0.y *= n0; w0.z *= n0; w0.w *= n0;
    w1.x *= n1; w1.y *= n1; w1.z *= n1; w1.w *= n1;
    w2.x *= n2; w2.y *= n2; w2.z *= n2; w2.w *= n2;
    w3.x *= n3; w3.y *= n3; w3.z *= n3; w3.w *= n3;

    const float4* xp = (const float4*)x + (size_t)b * TT * D4 + tid;
    float4*       op = (float4*)out     + (size_t)b * TT * D4 + tid;

    const float4 Z = make_float4(0.f, 0.f, 0.f, 0.f);

    // ---- preload: 3 halo rows + phase-0's 4 rows (7 loads in flight) ----
    float4 h0 = Z, h1 = Z, h2 = Z;
    if (blockIdx.x > 0) {
        h0 = __ldg(xp + (size_t)(t0 - 3) * D4);
        h1 = __ldg(xp + (size_t)(t0 - 2) * D4);
        h2 = __ldg(xp + (size_t)(t0 - 1) * D4);
    }
    float4 xv0 = __ldg(xp + (size_t)(t0 + 0) * D4);
    float4 xv1 = __ldg(xp + (size_t)(t0 + 1) * D4);
    float4 xv2 = __ldg(xp + (size_t)(t0 + 2) * D4);
    float4 xv3 = __ldg(xp + (size_t)(t0 + 3) * D4);

    // ---- preamble reduction: rinv for the 3 halo rows (into fin[1]) ----
    {
        float s0 = warp_sum(sq4(h0));
        float s1 = warp_sum(sq4(h1));
        float s2 = warp_sum(sq4(h2));
        if (lane == 0) {
            part[0 * 16 + wrp] = s0;
            part[1 * 16 + wrp] = s1;
            part[2 * 16 + wrp] = s2;
        }
        __syncthreads();
        if (wrp < 3) {
            float v = (lane < 16) ? part[wrp * 16 + lane] : 0.f;
            v += __shfl_xor_sync(0xffffffffu, v, 8);
            v += __shfl_xor_sync(0xffffffffu, v, 4);
            v += __shfl_xor_sync(0xffffffffu, v, 2);
            v += __shfl_xor_sync(0xffffffffu, v, 1);
            if (lane == 0)
                ((float*)&fin[1])[wrp] = rsqrtf(v * (1.0f / (float)DD) + EPS);
        }
        __syncthreads();
    }
    float4 rvh = fin[1];

    // Normalized sliding window: y0=y[t-3], y1=y[t-2], y2=y[t-1]
    float4 y0 = make_float4(h0.x * rvh.x, h0.y * rvh.x, h0.z * rvh.x, h0.w * rvh.x);
    float4 y1 = make_float4(h1.x * rvh.y, h1.y * rvh.y, h1.z * rvh.y, h1.w * rvh.y);
    float4 y2 = make_float4(h2.x * rvh.z, h2.y * rvh.z, h2.z * rvh.z, h2.w * rvh.z);

    // ---- main loop: 16 phases x 4 rows ----
    #pragma unroll 1
    for (int ph = 0; ph < NPH; ph++) {
        const int tb = t0 + ph * 4;
        const bool more = (ph + 1 < NPH);

        // Stage 1: warp partials for 4 rows (shfl chains pipeline).
        float s0 = warp_sum(sq4(xv0));
        float s1 = warp_sum(sq4(xv1));
        float s2 = warp_sum(sq4(xv2));
        float s3 = warp_sum(sq4(xv3));
        if (lane == 0) {
            part[0 * 16 + wrp] = s0;
            part[1 * 16 + wrp] = s1;
            part[2 * 16 + wrp] = s2;
            part[3 * 16 + wrp] = s3;
        }
        __syncthreads();

        // Stage 2: warp j finishes row j, stores rinv directly.
        if (wrp < 4) {
            float v = (lane < 16) ? part[wrp * 16 + lane] : 0.f;
            v += __shfl_xor_sync(0xffffffffu, v, 8);
            v += __shfl_xor_sync(0xffffffffu, v, 4);
            v += __shfl_xor_sync(0xffffffffu, v, 2);
            v += __shfl_xor_sync(0xffffffffu, v, 1);
            if (lane == 0)
                ((float*)&fin[ph & 1])[wrp] = rsqrtf(v * (1.0f / (float)DD) + EPS);
        }
        __syncthreads();

        const float4 rv = fin[ph & 1];   // one LDS.128: 4 rinvs

        // Row 0
        {
            float4 y3 = make_float4(xv0.x * rv.x, xv0.y * rv.x, xv0.z * rv.x, xv0.w * rv.x);
            xv0 = more ? __ldg(xp + (size_t)(tb + 4) * D4) : Z;   // refill, keeps MLP=4
            float4 o;
            o.x = w0.x * y0.x + w0.y * y1.x + w0.z * y2.x + w0.w * y3.x;
            o.y = w1.x * y0.y + w1.y * y1.y + w1.z * y2.y + w1.w * y3.y;
            o.z = w2.x * y0.z + w2.y * y1.z + w2.z * y2.z + w2.w * y3.z;
            o.w = w3.x * y0.w + w3.y * y1.w + w3.z * y2.w + w3.w * y3.w;
            o.x *= fast_sigmoid(o.x); o.y *= fast_sigmoid(o.y);
            o.z *= fast_sigmoid(o.z); o.w *= fast_sigmoid(o.w);
            op[(size_t)(tb + 0) * D4] = o;
            y0 = y1; y1 = y2; y2 = y3;
        }
        // Row 1
        {
            float4 y3 = make_float4(xv1.x * rv.y, xv1.y * rv.y, xv1.z * rv.y, xv1.w * rv.y);
            xv1 = more ? __ldg(xp + (size_t)(tb + 5) * D4) : Z;
            float4 o;
            o.x = w0.x * y0.x + w0.y * y1.x + w0.z * y2.x + w0.w * y3.x;
            o.y = w1.x * y0.y + w1.y * y1.y + w1.z * y2.y + w1.w * y3.y;
            o.z = w2.x * y0.z + w2.y * y1.z + w2.z * y2.z + w2.w * y3.z;
            o.w = w3.x * y0.w + w3.y * y1.w + w3.z * y2.w + w3.w * y3.w;
            o.x *= fast_sigmoid(o.x); o.y *= fast_sigmoid(o.y);
            o.z *= fast_sigmoid(o.z); o.w *= fast_sigmoid(o.w);
            op[(size_t)(tb + 1) * D4] = o;
            y0 = y1; y1 = y2; y2 = y3;
        }
        // Row 2
        {
            float4 y3 = make_float4(xv2.x * rv.z, xv2.y * rv.z, xv2.z * rv.z, xv2.w * rv.z);
            xv2 = more ? __ldg(xp + (size_t)(tb + 6) * D4) : Z;
            float4 o;
            o.x = w0.x * y0.x + w0.y * y1.x + w0.z * y2.x + w0.w * y3.x;
            o.y = w1.x * y0.y + w1.y * y1.y + w1.z * y2.y + w1.w * y3.y;
            o.z = w2.x * y0.z + w2.y * y1.z + w2.z * y2.z + w2.w * y3.z;
            o.w = w3.x * y0.w + w3.y * y1.w + w3.z * y2.w + w3.w * y3.w;
            o.x *= fast_sigmoid(o.x); o.y *= fast_sigmoid(o.y);
            o.z *= fast_sigmoid(o.z); o.w *= fast_sigmoid(o.w);
            op[(size_t)(tb + 2) * D4] = o;
            y0 = y1; y1 = y2; y2 = y3;
        }
        // Row 3
        {
            float4 y3 = make_float4(xv3.x * rv.w, xv3.y * rv.w, xv3.z * rv.w, xv3.w * rv.w);
            xv3 = more ? __ldg(xp + (size_t)(tb + 7) * D4) : Z;
            float4 o;
            o.x = w0.x * y0.x + w0.y * y1.x + w0.z * y2.x + w0.w * y3.x;
            o.y = w1.x * y0.y + w1.y * y1.y + w1.z * y2.y + w1.w * y3.y;
            o.z = w2.x * y0.z + w2.y * y1.z + w2.z * y2.z + w2.w * y3.z;
            o.w = w3.x * y0.w + w3.y * y1.w + w3.z * y2.w + w3.w * y3.w;
            o.x *= fast_sigmoid(o.x); o.y *= fast_sigmoid(o.y);
            o.z *= fast_sigmoid(o.z); o.w *= fast_sigmoid(o.w);
            op[(size_t)(tb + 3) * D4] = o;
            y0 = y1; y1 = y2; y2 = y3;
        }
    }
}

extern "C" void kernel_launch(void* const* d_in, const int* in_sizes, int n_in,
                              void* d_out, int out_size) {
    const float* x  = (const float*)d_in[0];   // [B, T, D] fp32
    const float* nw = (const float*)d_in[1];   // [D] fp32
    const float* cw = (const float*)d_in[2];   // [D, 1, K=4] fp32
    float* out = (float*)d_out;                // [B, T, D] fp32

    dim3 grid(TT / CT, BB);
    fused_rms_dwconv_silu<<<grid, 512>>>(x, nw, cw, out);
}

// round 8
// speedup vs baseline: 1.4677x; 1.3161x over previous
#include <cuda_runtime.h>
#include <cuda_bf16.h>
#include <cstdint>

// Problem constants
#define BB 4
#define TT 4096
#define DD 2048
#define D4 512            // DD/4 float4 lanes
#define CT 64             // output rows per block
#define NPH 16            // phases of 4 rows
#define EPS 1e-5f

#define ROWB   8192       // bytes per row in smem (512 * 16)
#define STAGEB 32768      // 4 rows per stage
#define NSTAGE 3
#define PARTOFF (NSTAGE * STAGEB)       // 98304
#define SMEMSZ  (PARTOFF + 64 * 4)      // + 64 partials

__device__ __forceinline__ float fast_sigmoid(float v) {
    float t;
    asm("tanh.approx.f32 %0, %1;" : "=f"(t) : "f"(v * 0.5f));
    return fmaf(t, 0.5f, 0.5f);
}

__device__ __forceinline__ float warp_sum(float v) {
    #pragma unroll
    for (int o = 16; o; o >>= 1) v += __shfl_xor_sync(0xffffffffu, v, o);
    return v;
}

__device__ __forceinline__ float sq4(float4 a) {
    return a.x * a.x + a.y * a.y + a.z * a.z + a.w * a.w;
}

__device__ __forceinline__ void cpa16(unsigned int saddr, const float4* g) {
    asm volatile("cp.async.cg.shared.global [%0], [%1], 16;" :: "r"(saddr), "l"(g) : "memory");
}
__device__ __forceinline__ void cpa_commit() {
    asm volatile("cp.async.commit_group;" ::: "memory");
}
__device__ __forceinline__ void cpa_wait1() {
    asm volatile("cp.async.wait_group 1;" ::: "memory");
}

#define ROW_BODY(XV, R, TOFF)                                                   \
    {                                                                           \
        float4 y3 = make_float4(XV.x * R, XV.y * R, XV.z * R, XV.w * R);        \
        float4 o;                                                               \
        o.x = w0.x * y0.x + w0.y * y1.x + w0.z * y2.x + w0.w * y3.x;            \
        o.y = w1.x * y0.y + w1.y * y1.y + w1.z * y2.y + w1.w * y3.y;            \
        o.z = w2.x * y0.z + w2.y * y1.z + w2.z * y2.z + w2.w * y3.z;            \
        o.w = w3.x * y0.w + w3.y * y1.w + w3.z * y2.w + w3.w * y3.w;            \
        o.x *= fast_sigmoid(o.x); o.y *= fast_sigmoid(o.y);                     \
        o.z *= fast_sigmoid(o.z); o.w *= fast_sigmoid(o.w);                     \
        __stcs(op + (size_t)(TOFF) * D4, o);                                    \
        y0 = y1; y1 = y2; y2 = y3;                                              \
    }

__global__ __launch_bounds__(512, 2)
void fused_rms_dwconv_silu(const float* __restrict__ x,
                           const float* __restrict__ nw,
                           const float* __restrict__ cw,
                           float* __restrict__ out) {
    extern __shared__ unsigned char dynsmem[];
    float* part = (float*)(dynsmem + PARTOFF);
    const unsigned int sbase = (unsigned int)__cvta_generic_to_shared(dynsmem);

    const int tid  = threadIdx.x;          // one float4 column of D
    const int lane = tid & 31;
    const int wrp  = tid >> 5;             // 0..15
    const int b    = blockIdx.y;
    const int t0   = blockIdx.x * CT;
    const int d    = tid * 4;

    // Conv taps with norm_weight folded in.
    float4 w0 = *(const float4*)(cw + (size_t)(d + 0) * 4);
    float4 w1 = *(const float4*)(cw + (size_t)(d + 1) * 4);
    float4 w2 = *(const float4*)(cw + (size_t)(d + 2) * 4);
    float4 w3 = *(const float4*)(cw + (size_t)(d + 3) * 4);
    const float n0 = nw[d], n1 = nw[d + 1], n2 = nw[d + 2], n3 = nw[d + 3];
    w0.x *= n0; w0.y *= n0; w0.z *= n0; w0.w *= n0;
    w1.x *= n1; w1.y *= n1; w1.z *= n1; w1.w *= n1;
    w2.x *= n2; w2.y *= n2; w2.z *= n2; w2.w *= n2;
    w3.x *= n3; w3.y *= n3; w3.z *= n3; w3.w *= n3;

    const float4* xp = (const float4*)x + (size_t)b * TT * D4 + tid;
    float4*       op = (float4*)out     + (size_t)b * TT * D4 + tid;
    const float4  Z  = make_float4(0.f, 0.f, 0.f, 0.f);

    // ---- prolog: kick G0 (phase 0 rows -> stage 0) and G1 (phase 1 -> stage 1)
    {
        unsigned int dst0 = sbase + 0 * STAGEB + tid * 16;
        const float4* s0 = xp + (size_t)(t0 + 0) * D4;
        cpa16(dst0 + 0 * ROWB, s0 + 0 * D4);
        cpa16(dst0 + 1 * ROWB, s0 + 1 * D4);
        cpa16(dst0 + 2 * ROWB, s0 + 2 * D4);
        cpa16(dst0 + 3 * ROWB, s0 + 3 * D4);
        cpa_commit();
        unsigned int dst1 = sbase + 1 * STAGEB + tid * 16;
        const float4* s1 = xp + (size_t)(t0 + 4) * D4;
        cpa16(dst1 + 0 * ROWB, s1 + 0 * D4);
        cpa16(dst1 + 1 * ROWB, s1 + 1 * D4);
        cpa16(dst1 + 2 * ROWB, s1 + 2 * D4);
        cpa16(dst1 + 3 * ROWB, s1 + 3 * D4);
        cpa_commit();
    }

    // ---- halo rows t0-3..t0-1 (plain LDG, overlaps with cp.async) ----
    float4 h0 = Z, h1 = Z, h2 = Z;
    if (blockIdx.x > 0) {
        h0 = __ldg(xp + (size_t)(t0 - 3) * D4);
        h1 = __ldg(xp + (size_t)(t0 - 2) * D4);
        h2 = __ldg(xp + (size_t)(t0 - 1) * D4);
    }
    {
        float s0 = warp_sum(sq4(h0));
        float s1 = warp_sum(sq4(h1));
        float s2 = warp_sum(sq4(h2));
        if (lane == 0) {
            part[0 * 16 + wrp] = s0;
            part[1 * 16 + wrp] = s1;
            part[2 * 16 + wrp] = s2;
        }
    }
    __syncthreads();
    float4 y0, y1, y2;
    {
        float vlo = part[lane];                              // rows h0,h1
        float vhi = (lane < 16) ? part[lane + 32] : 0.f;     // row h2
        #pragma unroll
        for (int o = 8; o; o >>= 1) {
            vlo += __shfl_xor_sync(0xffffffffu, vlo, o);
            vhi += __shfl_xor_sync(0xffffffffu, vhi, o);
        }
        float rlo = rsqrtf(vlo * (1.0f / (float)DD) + EPS);
        float rhi = rsqrtf(vhi * (1.0f / (float)DD) + EPS);
        float rh0 = __shfl_sync(0xffffffffu, rlo, 0);
        float rh1 = __shfl_sync(0xffffffffu, rlo, 16);
        float rh2 = __shfl_sync(0xffffffffu, rhi, 0);
        y0 = make_float4(h0.x * rh0, h0.y * rh0, h0.z * rh0, h0.w * rh0);
        y1 = make_float4(h1.x * rh1, h1.y * rh1, h1.z * rh1, h1.w * rh1);
        y2 = make_float4(h2.x * rh2, h2.y * rh2, h2.z * rh2, h2.w * rh2);
    }
    cpa_wait1();          // G0 complete (G1 may pend)
    __syncthreads();      // publish G0 data + protect part[]

    // ---- main loop: 16 phases x 4 rows, 3-stage ring, distance-2 prefetch ----
    #pragma unroll 1
    for (int p = 0; p < NPH; p++) {
        const int tb = t0 + p * 4;

        // 1. prefetch phase p+2 into stage (p+2)%3 (free: that stage's reads
        //    finished before phase p-1's bar A)
        if (p + 2 < NPH) {
            unsigned int dst = sbase + ((p + 2) % 3) * STAGEB + tid * 16;
            const float4* src = xp + (size_t)(t0 + (p + 2) * 4) * D4;
            cpa16(dst + 0 * ROWB, src + 0 * D4);
            cpa16(dst + 1 * ROWB, src + 1 * D4);
            cpa16(dst + 2 * ROWB, src + 2 * D4);
            cpa16(dst + 3 * ROWB, src + 3 * D4);
        }
        cpa_commit();   // empty group when guarded out: keeps FIFO aligned

        // 2. stage 1: read this phase's 4 rows from smem, warp partials
        const float4* buf = (const float4*)(dynsmem + (p % 3) * STAGEB);
        float4 xv0 = buf[0 * D4 + tid];
        float4 xv1 = buf[1 * D4 + tid];
        float4 xv2 = buf[2 * D4 + tid];
        float4 xv3 = buf[3 * D4 + tid];
        float s0 = warp_sum(sq4(xv0));
        float s1 = warp_sum(sq4(xv1));
        float s2 = warp_sum(sq4(xv2));
        float s3 = warp_sum(sq4(xv3));
        if (lane == 0) {
            part[0 * 16 + wrp] = s0;
            part[1 * 16 + wrp] = s1;
            part[2 * 16 + wrp] = s2;
            part[3 * 16 + wrp] = s3;
        }
        __syncthreads();   // bar A: partials visible, stage p%3 reads done

        // 3. redundant finish: every warp computes all 4 rinvs (no 2nd bar)
        float vlo = part[lane];          // rows 0 (lanes 0-15), 1 (16-31)
        float vhi = part[lane + 32];     // rows 2, 3
        #pragma unroll
        for (int o = 8; o; o >>= 1) {
            vlo += __shfl_xor_sync(0xffffffffu, vlo, o);
            vhi += __shfl_xor_sync(0xffffffffu, vhi, o);
        }
        float rlo = rsqrtf(vlo * (1.0f / (float)DD) + EPS);
        float rhi = rsqrtf(vhi * (1.0f / (float)DD) + EPS);
        float r0 = __shfl_sync(0xffffffffu, rlo, 0);
        float r1 = __shfl_sync(0xffffffffu, rlo, 16);
        float r2 = __shfl_sync(0xffffffffu, rhi, 0);
        float r3 = __shfl_sync(0xffffffffu, rhi, 16);

        // 4. conv + SiLU + streaming stores (overlaps in-flight cp.async)
        ROW_BODY(xv0, r0, tb + 0);
        ROW_BODY(xv1, r1, tb + 1);
        ROW_BODY(xv2, r2, tb + 2);
        ROW_BODY(xv3, r3, tb + 3);

        // 5. ensure next phase's group done, publish to all threads
        cpa_wait1();
        __syncthreads();   // bar B
    }
}

extern "C" void kernel_launch(void* const* d_in, const int* in_sizes, int n_in,
                              void* d_out, int out_size) {
    const float* x  = (const float*)d_in[0];   // [B, T, D] fp32
    const float* nw = (const float*)d_in[1];   // [D] fp32
    const float* cw = (const float*)d_in[2];   // [D, 1, K=4] fp32
    float* out = (float*)d_out;                // [B, T, D] fp32

    cudaFuncSetAttribute(fused_rms_dwconv_silu,
                         cudaFuncAttributeMaxDynamicSharedMemorySize, SMEMSZ);

    dim3 grid(TT / CT, BB);
    fused_rms_dwconv_silu<<<grid, 512, SMEMSZ>>>(x, nw, cw, out);
}